// round 13
// baseline (speedup 1.0000x reference)
#include <cuda_runtime.h>
#include <cuda_bf16.h>
#include <math.h>
#include <cstdint>

#define BB 64
#define HH 512
#define AA 256
#define VV 10000
#define TT 151
#define LL 49
#define G3 1536
#define MM (BB*TT)
#define NBLK 128

typedef unsigned long long ull;

#define FMA2(acc, av, wv) asm("fma.rn.f32x2 %0, %1, %2, %0;" : "+l"(acc) : "l"(av), "l"(wv))

// ------------------------- device scratch (static, no allocs) -------------------------
__device__ float g_enc [BB*LL*HH];       // [b][l][d]  == row-major [3136][512]
__device__ float g_att1[BB*LL*AA];       // [b][l][a]
__device__ float g_h   [BB*HH];
__device__ float g_inp [BB*HH];
__device__ float g_ctx [BB*HH];
__device__ float g_comb[BB*HH];
__device__ float g_att2p[8][BB*AA];      // att2 k-split partials
__device__ float g_combp[16][BB*HH];     // comb k-split partials
__device__ float g_ghp [4][BB*G3];       // gh partials
__device__ float g_gip [4][BB*G3];       // gi partials
__device__ float g_ghsum[BB*G3];         // reduced gh + b_hh
__device__ float g_seq [BB*TT*HH];       // [b][t][d] == row-major [9664][512]
__device__ ull   g_tokkey[MM];
__device__ unsigned g_flag[NBLK*32];     // one 128B slot per CTA

__device__ __forceinline__ unsigned ordf(float f){
    unsigned u = __float_as_uint(f);
    return (u & 0x80000000u) ? ~u : (u | 0x80000000u);
}

// ------------------------- grid barrier: per-CTA flag slots, tight spin (proven round-9) ----
__device__ __forceinline__ void gsync(int epoch){
    __syncthreads();
    if (threadIdx.x == 0){
        asm volatile("st.release.gpu.global.u32 [%0], %1;"
                     :: "l"(&g_flag[blockIdx.x*32]), "r"((unsigned)epoch) : "memory");
    }
    if (threadIdx.x < NBLK){
        unsigned v;
        do {
            asm volatile("ld.acquire.gpu.global.u32 %0, [%1];"
                         : "=r"(v) : "l"(&g_flag[threadIdx.x*32]) : "memory");
        } while (v < (unsigned)epoch);
    }
    __syncthreads();
}

// ------------------------- reset flags + token keys -------------------------
__global__ void k_rst(){
    int i = blockIdx.x*256 + threadIdx.x;
    if (i < NBLK*32) g_flag[i] = 0u;
    if (i < MM) g_tokkey[i] = 0ULL;
}

// ------------------------- P0: inp0 = embed[start], seq[:,0,:] -------------------------
__global__ void k_p0(const float* __restrict__ embed, const int* __restrict__ start){
    int b = blockIdx.x;
    int st = start ? start[0] : 1;
    for (int d = threadIdx.x; d < HH; d += blockDim.x){
        float v = embed[(size_t)st*HH + d];
        g_inp[b*HH + d] = v;
        g_seq[((size_t)b*TT + 0)*HH + d] = v;
    }
}

// ------------------------- 64x64 microtile, FFMA2 packed (Ws stride 66) -------------------------
__device__ __forceinline__ void mt32_2(const float* __restrict__ As, const float* __restrict__ Ws,
                                       int tx, int ty, ull acc2[4][2]){
    #pragma unroll 8
    for (int kk = 0; kk < 32; kk++){
        ull a2[4], w2[2];
        #pragma unroll
        for (int i = 0; i < 4; i++){
            float av = As[(ty*4+i)*33 + kk];
            asm("mov.b64 %0, {%1, %2};" : "=l"(a2[i]) : "f"(av), "f"(av));
        }
        w2[0] = *(const ull*)&Ws[kk*66 + tx*4];
        w2[1] = *(const ull*)&Ws[kk*66 + tx*4 + 2];
        #pragma unroll
        for (int i = 0; i < 4; i++){
            FMA2(acc2[i][0], a2[i], w2[0]);
            FMA2(acc2[i][1], a2[i], w2[1]);
        }
    }
}

__device__ __forceinline__ void unpack44(ull acc2[4][2], float acc[4][4]){
    #pragma unroll
    for (int i = 0; i < 4; i++){
        asm("mov.b64 {%0, %1}, %2;" : "=f"(acc[i][0]), "=f"(acc[i][1]) : "l"(acc2[i][0]));
        asm("mov.b64 {%0, %1}, %2;" : "=f"(acc[i][2]), "=f"(acc[i][3]) : "l"(acc2[i][1]));
    }
}

// ------------------------- P1: enc = X^T @ W_fp + b_fp (tiled GEMM, M=3136) -------------------------
__global__ void __launch_bounds__(256)
k_p1(const float* __restrict__ X, const float* __restrict__ Wfp, const float* __restrict__ bfp){
    __shared__ __align__(16) float As[64*33];
    __shared__ __align__(16) float Ws[32*66];
    int m0 = blockIdx.x*64, n0 = blockIdx.y*64;
    int tid = threadIdx.x, tx = tid & 15, ty = tid >> 4;
    ull acc2[4][2] = {{0ULL,0ULL},{0ULL,0ULL},{0ULL,0ULL},{0ULL,0ULL}};
    for (int kc = 0; kc < HH; kc += 32){
        __syncthreads();
        #pragma unroll
        for (int i = 0; i < 8; i++){
            int idx = tid + i*256; int mm = idx >> 5, kk = idx & 31;
            int m = m0 + mm; int b = m / LL; int l = m - b*LL;
            As[mm*33 + kk] = X[((size_t)b*HH + kc + kk)*LL + l];
        }
        #pragma unroll
        for (int i = 0; i < 8; i++){
            int idx = tid + i*256; int kk = idx >> 6, n = idx & 63;
            Ws[kk*66 + n] = Wfp[(size_t)(kc+kk)*HH + n0 + n];
        }
        __syncthreads();
        mt32_2(As, Ws, tx, ty, acc2);
    }
    float acc[4][4]; unpack44(acc2, acc);
    #pragma unroll
    for (int j = 0; j < 4; j++){
        float bv = bfp[n0 + tx*4 + j];
        #pragma unroll
        for (int i = 0; i < 4; i++)
            g_enc[(size_t)(m0 + ty*4 + i)*HH + n0 + tx*4 + j] = acc[i][j] + bv;
    }
}

// ------------------------- h0 = mean over l of enc -------------------------
__global__ void k_h0(){
    int b = blockIdx.x;
    int d = blockIdx.y*128 + threadIdx.x;
    float s = 0.f;
    #pragma unroll 7
    for (int l = 0; l < LL; l++)
        s += g_enc[((size_t)b*LL + l)*HH + d];
    g_h[b*HH + d] = s * (1.f/(float)LL);
}

// ------------------------- P2: att1 = enc @ W_enc + b_enc (tiled GEMM) -------------------------
__global__ void __launch_bounds__(256)
k_p2(const float* __restrict__ Wenc, const float* __restrict__ benc){
    __shared__ __align__(16) float As[64*33];
    __shared__ __align__(16) float Ws[32*66];
    int m0 = blockIdx.x*64, n0 = blockIdx.y*64;
    int tid = threadIdx.x, tx = tid & 15, ty = tid >> 4;
    ull acc2[4][2] = {{0ULL,0ULL},{0ULL,0ULL},{0ULL,0ULL},{0ULL,0ULL}};
    for (int kc = 0; kc < HH; kc += 32){
        __syncthreads();
        #pragma unroll
        for (int i = 0; i < 8; i++){
            int idx = tid + i*256; int mm = idx >> 5, kk = idx & 31;
            As[mm*33 + kk] = g_enc[(size_t)(m0 + mm)*HH + kc + kk];
        }
        #pragma unroll
        for (int i = 0; i < 8; i++){
            int idx = tid + i*256; int kk = idx >> 6, n = idx & 63;
            Ws[kk*66 + n] = Wenc[(size_t)(kc+kk)*AA + n0 + n];
        }
        __syncthreads();
        mt32_2(As, Ws, tx, ty, acc2);
    }
    float acc[4][4]; unpack44(acc2, acc);
    #pragma unroll
    for (int j = 0; j < 4; j++){
        float bv = benc[n0 + tx*4 + j];
        #pragma unroll
        for (int i = 0; i < 4; i++)
            g_att1[(size_t)(m0 + ty*4 + i)*AA + n0 + tx*4 + j] = acc[i][j] + bv;
    }
}

// ------------------------- persistent step kernel: 150 steps, 6 phases, prefetch + FFMA2 ------------
__global__ void __launch_bounds__(256)
k_step(const float* __restrict__ Wdec,  const float* __restrict__ bdec,
       const float* __restrict__ Wfull, const float* __restrict__ bfull,
       const float* __restrict__ Wcomb, const float* __restrict__ bcomb,
       const float* __restrict__ Wih,   const float* __restrict__ bih,
       const float* __restrict__ Whh,   const float* __restrict__ bhh)
{
    __shared__ __align__(16) float As[64*33];
    __shared__ __align__(16) float Ws[32*66];
    const int blk = blockIdx.x, tid = threadIdx.x;
    const int tx = tid & 15, ty = tid >> 4;
    const int warp = tid >> 5, lane = tid & 31;
    int ep = 0;

    for (int t = 1; t < TT; t++){
        // ======== P1: att2 partials (blk<32) + gh partials (blk>=32) ========
        if (blk < 32){
            int at = blk & 3, ks = blk >> 2;
            int n0 = at*64, k0 = ks*64;
            ull acc2[4][2] = {{0ULL,0ULL},{0ULL,0ULL},{0ULL,0ULL},{0ULL,0ULL}};
            float pa[8], pw[8];
            #pragma unroll
            for (int i = 0; i < 8; i++){
                int idx = tid + i*256; int b = idx >> 5, kk = idx & 31;
                pa[i] = __ldcg(&g_h[b*HH + k0 + kk]);
            }
            #pragma unroll
            for (int i = 0; i < 8; i++){
                int idx = tid + i*256; int n = idx & 63, kk = idx >> 6;
                pw[i] = Wdec[(size_t)(k0+kk)*AA + n0 + n];
            }
            #pragma unroll
            for (int s = 0; s < 2; s++){
                __syncthreads();
                #pragma unroll
                for (int i = 0; i < 8; i++){
                    int idx = tid + i*256; int b = idx >> 5, kk = idx & 31;
                    As[b*33 + kk] = pa[i];
                }
                #pragma unroll
                for (int i = 0; i < 8; i++){
                    int idx = tid + i*256; int n = idx & 63, kk = idx >> 6;
                    Ws[kk*66 + n] = pw[i];
                }
                __syncthreads();
                if (s == 0){
                    int kb = k0 + 32;
                    #pragma unroll
                    for (int i = 0; i < 8; i++){
                        int idx = tid + i*256; int b = idx >> 5, kk = idx & 31;
                        pa[i] = __ldcg(&g_h[b*HH + kb + kk]);
                    }
                    #pragma unroll
                    for (int i = 0; i < 8; i++){
                        int idx = tid + i*256; int n = idx & 63, kk = idx >> 6;
                        pw[i] = Wdec[(size_t)(kb+kk)*AA + n0 + n];
                    }
                }
                mt32_2(As, Ws, tx, ty, acc2);
            }
            float acc[4][4]; unpack44(acc2, acc);
            float* outp = g_att2p[ks];
            #pragma unroll
            for (int i = 0; i < 4; i++)
                #pragma unroll
                for (int j = 0; j < 4; j++)
                    outp[(ty*4+i)*AA + n0 + tx*4 + j] = acc[i][j];
        } else {
            int rem = blk - 32;
            int jt = rem % 24, ks = rem / 24;
            int j0 = jt*64, k0 = ks*128;
            ull acc2[4][2] = {{0ULL,0ULL},{0ULL,0ULL},{0ULL,0ULL},{0ULL,0ULL}};
            float pa[8], pw[8];
            #pragma unroll
            for (int i = 0; i < 8; i++){
                int idx = tid + i*256; int b = idx >> 5, kk = idx & 31;
                pa[i] = __ldcg(&g_h[b*HH + k0 + kk]);
            }
            #pragma unroll
            for (int i = 0; i < 8; i++){
                int idx = tid + i*256; int kk = idx & 31, j = idx >> 5;
                pw[i] = Whh[(size_t)(j0+j)*HH + k0 + kk];
            }
            #pragma unroll
            for (int s = 0; s < 4; s++){
                __syncthreads();
                #pragma unroll
                for (int i = 0; i < 8; i++){
                    int idx = tid + i*256; int b = idx >> 5, kk = idx & 31;
                    As[b*33 + kk] = pa[i];
                }
                #pragma unroll
                for (int i = 0; i < 8; i++){
                    int idx = tid + i*256; int kk = idx & 31, j = idx >> 5;
                    Ws[kk*66 + j] = pw[i];
                }
                __syncthreads();
                if (s < 3){
                    int kb = k0 + (s+1)*32;
                    #pragma unroll
                    for (int i = 0; i < 8; i++){
                        int idx = tid + i*256; int b = idx >> 5, kk = idx & 31;
                        pa[i] = __ldcg(&g_h[b*HH + kb + kk]);
                    }
                    #pragma unroll
                    for (int i = 0; i < 8; i++){
                        int idx = tid + i*256; int kk = idx & 31, j = idx >> 5;
                        pw[i] = Whh[(size_t)(j0+j)*HH + kb + kk];
                    }
                }
                mt32_2(As, Ws, tx, ty, acc2);
            }
            float acc[4][4]; unpack44(acc2, acc);
            float* outp = g_ghp[ks];
            #pragma unroll
            for (int i = 0; i < 4; i++)
                #pragma unroll
                for (int j = 0; j < 4; j++)
                    outp[(ty*4+i)*G3 + j0 + tx*4 + j] = acc[i][j];
        }
        ep++; gsync(ep);

        // ======== P2: per-batch attention (blk<64) | gh reduce (blk>=64) ========
        if (blk < 64){
            int b = blk;
            {
                int a = tid;
                float s = bdec[a];
                #pragma unroll
                for (int p = 0; p < 8; p++) s += __ldcg(&g_att2p[p][b*AA + a]);
                As[a] = s;
            }
            __syncthreads();
            for (int l = warp; l < LL; l += 8){
                const float* a1p = g_att1 + ((size_t)b*LL + l)*AA;
                float s = 0.f;
                #pragma unroll
                for (int k = 0; k < 8; k++){
                    int a = lane + k*32;
                    s = fmaf(tanhf(a1p[a] + As[a]), Wfull[a], s);
                }
                #pragma unroll
                for (int o = 16; o > 0; o >>= 1) s += __shfl_xor_sync(0xffffffffu, s, o);
                if (lane == 0) As[256 + l] = s + bfull[0];
            }
            __syncthreads();
            if (warp == 0){
                int l1 = lane, l2 = lane + 32;
                float e1 = (l1 < LL) ? As[256+l1] : -1e30f;
                float e2 = (l2 < LL) ? As[256+l2] : -1e30f;
                float m = fmaxf(e1, e2);
                #pragma unroll
                for (int o = 16; o > 0; o >>= 1) m = fmaxf(m, __shfl_xor_sync(0xffffffffu, m, o));
                float p1 = (l1 < LL) ? expf(e1 - m) : 0.f;
                float p2 = (l2 < LL) ? expf(e2 - m) : 0.f;
                float sm = p1 + p2;
                #pragma unroll
                for (int o = 16; o > 0; o >>= 1) sm += __shfl_xor_sync(0xffffffffu, sm, o);
                float inv = 1.f/sm;
                if (l1 < LL) As[320 + l1] = p1*inv;
                if (l2 < LL) As[320 + l2] = p2*inv;
            }
            __syncthreads();
            {
                int d0 = tid, d1 = tid + 256;
                const float* eb = g_enc + (size_t)b*LL*HH;
                float c0 = 0.f, c1 = 0.f;
                #pragma unroll 7
                for (int l = 0; l < LL; l++){
                    float al = As[320 + l];
                    c0 = fmaf(al, eb[l*HH + d0], c0);
                    c1 = fmaf(al, eb[l*HH + d1], c1);
                }
                g_ctx[b*HH + d0] = c0;
                g_ctx[b*HH + d1] = c1;
            }
        } else {
            int b = blk - 64;
            for (int j = tid; j < G3; j += 256){
                float s = bhh[j];
                #pragma unroll
                for (int p = 0; p < 4; p++) s += __ldcg(&g_ghp[p][b*G3 + j]);
                g_ghsum[b*G3 + j] = s;
            }
        }
        ep++; gsync(ep);

        // ======== P3: comb partials: [inp|ctx] @ W_comb ========
        {
            int nt = blk & 7, ks = blk >> 3;
            int n0 = nt*64, k0 = ks*64;
            ull acc2[4][2] = {{0ULL,0ULL},{0ULL,0ULL},{0ULL,0ULL},{0ULL,0ULL}};
            float pa[8], pw[8];
            #pragma unroll
            for (int i = 0; i < 8; i++){
                int idx = tid + i*256; int b = idx >> 5, kk = idx & 31;
                int k = k0 + kk;
                pa[i] = (k < HH) ? __ldcg(&g_inp[b*HH + k]) : __ldcg(&g_ctx[b*HH + (k - HH)]);
            }
            #pragma unroll
            for (int i = 0; i < 8; i++){
                int idx = tid + i*256; int n = idx & 63, kk = idx >> 6;
                pw[i] = Wcomb[(size_t)(k0+kk)*HH + n0 + n];
            }
            #pragma unroll
            for (int s = 0; s < 2; s++){
                __syncthreads();
                #pragma unroll
                for (int i = 0; i < 8; i++){
                    int idx = tid + i*256; int b = idx >> 5, kk = idx & 31;
                    As[b*33 + kk] = pa[i];
                }
                #pragma unroll
                for (int i = 0; i < 8; i++){
                    int idx = tid + i*256; int n = idx & 63, kk = idx >> 6;
                    Ws[kk*66 + n] = pw[i];
                }
                __syncthreads();
                if (s == 0){
                    int kb = k0 + 32;
                    #pragma unroll
                    for (int i = 0; i < 8; i++){
                        int idx = tid + i*256; int b = idx >> 5, kk = idx & 31;
                        int k = kb + kk;
                        pa[i] = (k < HH) ? __ldcg(&g_inp[b*HH + k]) : __ldcg(&g_ctx[b*HH + (k - HH)]);
                    }
                    #pragma unroll
                    for (int i = 0; i < 8; i++){
                        int idx = tid + i*256; int n = idx & 63, kk = idx >> 6;
                        pw[i] = Wcomb[(size_t)(kb+kk)*HH + n0 + n];
                    }
                }
                mt32_2(As, Ws, tx, ty, acc2);
            }
            float acc[4][4]; unpack44(acc2, acc);
            float* outp = g_combp[ks];
            #pragma unroll
            for (int i = 0; i < 4; i++)
                #pragma unroll
                for (int j = 0; j < 4; j++)
                    outp[(ty*4+i)*HH + n0 + tx*4 + j] = acc[i][j];
        }
        ep++; gsync(ep);

        // ======== P4: comb reduce + tanh ========
        {
            int i = blk*256 + tid;
            int n = i & 511;
            float s = bcomb[n];
            #pragma unroll
            for (int p = 0; p < 16; p++) s += __ldcg(&g_combp[p][i]);
            g_comb[i] = tanhf(s);
        }
        ep++; gsync(ep);

        // ======== P5: gi partials: comb @ W_ih^T (blk<96) ========
        if (blk < 96){
            int jt = blk % 24, ks = blk / 24;
            int j0 = jt*64, k0 = ks*128;
            ull acc2[4][2] = {{0ULL,0ULL},{0ULL,0ULL},{0ULL,0ULL},{0ULL,0ULL}};
            float pa[8], pw[8];
            #pragma unroll
            for (int i = 0; i < 8; i++){
                int idx = tid + i*256; int b = idx >> 5, kk = idx & 31;
                pa[i] = __ldcg(&g_comb[b*HH + k0 + kk]);
            }
            #pragma unroll
            for (int i = 0; i < 8; i++){
                int idx = tid + i*256; int kk = idx & 31, j = idx >> 5;
                pw[i] = Wih[(size_t)(j0+j)*HH + k0 + kk];
            }
            #pragma unroll
            for (int s = 0; s < 4; s++){
                __syncthreads();
                #pragma unroll
                for (int i = 0; i < 8; i++){
                    int idx = tid + i*256; int b = idx >> 5, kk = idx & 31;
                    As[b*33 + kk] = pa[i];
                }
                #pragma unroll
                for (int i = 0; i < 8; i++){
                    int idx = tid + i*256; int kk = idx & 31, j = idx >> 5;
                    Ws[kk*66 + j] = pw[i];
                }
                __syncthreads();
                if (s < 3){
                    int kb = k0 + (s+1)*32;
                    #pragma unroll
                    for (int i = 0; i < 8; i++){
                        int idx = tid + i*256; int b = idx >> 5, kk = idx & 31;
                        pa[i] = __ldcg(&g_comb[b*HH + kb + kk]);
                    }
                    #pragma unroll
                    for (int i = 0; i < 8; i++){
                        int idx = tid + i*256; int kk = idx & 31, j = idx >> 5;
                        pw[i] = Wih[(size_t)(j0+j)*HH + kb + kk];
                    }
                }
                mt32_2(As, Ws, tx, ty, acc2);
            }
            float acc[4][4]; unpack44(acc2, acc);
            float* outp = g_gip[ks];
            #pragma unroll
            for (int i = 0; i < 4; i++)
                #pragma unroll
                for (int j = 0; j < 4; j++)
                    outp[(ty*4+i)*G3 + j0 + tx*4 + j] = acc[i][j];
        }
        ep++; gsync(ep);

        // ======== P6: GRU pointwise -> h, inp, seq[t] ========
        {
            int i = blk*256 + tid;
            int b = i >> 9, j = i & 511;
            float gir = bih[j], giz = bih[512+j], gin = bih[1024+j];
            #pragma unroll
            for (int p = 0; p < 4; p++){
                const float* gi = g_gip[p] + (size_t)b*G3;
                gir += __ldcg(&gi[j]); giz += __ldcg(&gi[512+j]); gin += __ldcg(&gi[1024+j]);
            }
            const float* gh = g_ghsum + (size_t)b*G3;
            float ghr = __ldcg(&gh[j]), ghz = __ldcg(&gh[512+j]), ghn = __ldcg(&gh[1024+j]);
            float h = __ldcg(&g_h[i]);
            float r = 1.f/(1.f + expf(-(gir + ghr)));
            float z = 1.f/(1.f + expf(-(giz + ghz)));
            float n = tanhf(gin + r*ghn);
            float hn = (1.f - z)*n + z*h;
            g_h[i] = hn;
            g_inp[i] = hn;
            g_seq[((size_t)b*TT + t)*HH + j] = hn;
        }
        ep++; gsync(ep);
    }
}

// ------------------------- Final: res = seq @ W_proj + b_proj (FFMA2, dup-A) + fused argmax ---------
__global__ void __launch_bounds__(256, 2)
k_sf(const float* __restrict__ Wp, const float* __restrict__ bp, float* __restrict__ out){
    __shared__ __align__(16) ull   Asd[16*133];   // A tile pre-duplicated (a,a): 17,024 B
    __shared__ __align__(16) float Bs [16*132];   // 8,448 B
    int m0 = blockIdx.x*128, n0 = blockIdx.y*128;
    int tid = threadIdx.x, tx = tid & 15, ty = tid >> 4;
    ull acc2[8][4];
    #pragma unroll
    for (int i=0;i<8;i++)
        #pragma unroll
        for (int j=0;j<4;j++) acc2[i][j] = 0ULL;

    for (int kc = 0; kc < HH; kc += 16){
        __syncthreads();
        #pragma unroll
        for (int i = 0; i < 8; i++){
            int idx = tid + i*256;        // 128 m x 16 k
            int kk = idx & 15, m = idx >> 4;
            int r = m0 + m;
            float a = (r < MM) ? g_seq[(size_t)r*HH + kc + kk] : 0.f;
            *(float2*)&Asd[kk*133 + m] = make_float2(a, a);
        }
        #pragma unroll
        for (int i = 0; i < 8; i++){
            int idx = tid + i*256;        // 16 k x 128 n
            int n = idx & 127, kk = idx >> 7;
            int v = n0 + n;
            Bs[kk*132 + n] = (v < VV) ? Wp[(size_t)(kc+kk)*VV + v] : 0.f;
        }
        __syncthreads();
        #pragma unroll 4
        for (int kk = 0; kk < 16; kk++){
            ull a2[8], w2[4];
            #pragma unroll
            for (int i = 0; i < 8; i++)
                a2[i] = Asd[kk*133 + ty*8 + i];
            #pragma unroll
            for (int j = 0; j < 4; j++)
                w2[j] = *(const ull*)&Bs[kk*132 + tx*8 + 2*j];
            #pragma unroll
            for (int i = 0; i < 8; i++)
                #pragma unroll
                for (int j = 0; j < 4; j++)
                    FMA2(acc2[i][j], a2[i], w2[j]);
        }
    }
    float acc[8][8];
    #pragma unroll
    for (int i = 0; i < 8; i++)
        #pragma unroll
        for (int j = 0; j < 4; j++)
            asm("mov.b64 {%0, %1}, %2;" : "=f"(acc[i][2*j]), "=f"(acc[i][2*j+1]) : "l"(acc2[i][j]));
    #pragma unroll
    for (int j = 0; j < 8; j++){
        int v = n0 + tx*8 + j;
        float bj = (v < VV) ? bp[v] : 0.f;
        #pragma unroll
        for (int i = 0; i < 8; i++) acc[i][j] += bj;
    }

    // fused argmax: packed key = ordf(val)<<32 | (~v) -> max value, ties pick smaller v
    #pragma unroll
    for (int i = 0; i < 8; i++){
        int r = m0 + ty*8 + i;
        ull best = 0ULL;
        #pragma unroll
        for (int j = 0; j < 8; j++){
            int v = n0 + tx*8 + j;
            if (v < VV){
                ull key = ((ull)ordf(acc[i][j]) << 32) | (ull)(0xFFFFFFFFu - (unsigned)v);
                if (key > best) best = key;
            }
        }
        #pragma unroll
        for (int o = 8; o > 0; o >>= 1){
            ull other = __shfl_xor_sync(0xffffffffu, best, o);
            if (other > best) best = other;
        }
        if (tx == 0 && r < MM) atomicMax(&g_tokkey[r], best);
    }

    // transposed store via smem (32 output columns per pass), reuse Asd region
    float* sbuf = (float*)Asd;            // [32][129] = 16,512 B <= 17,024 B
    int lane = tid & 31, cbase = tid >> 5;
    for (int cg = 0; cg < 4; cg++){
        __syncthreads();
        if ((tx >> 2) == cg){
            #pragma unroll
            for (int j = 0; j < 8; j++){
                int cl = (tx & 3)*8 + j;
                #pragma unroll
                for (int i = 0; i < 8; i++)
                    sbuf[cl*129 + ty*8 + i] = acc[i][j];
            }
        }
        __syncthreads();
        #pragma unroll
        for (int cc = 0; cc < 4; cc++){
            int cl = cbase + cc*8;        // 0..31
            int v = n0 + cg*32 + cl;
            if (v < VV){
                #pragma unroll
                for (int q = 0; q < 4; q++){
                    int m = lane + q*32;
                    int r = m0 + m;
                    if (r < MM){
                        int b = r / TT;
                        int t = r - b*TT;
                        out[(size_t)b*VV*TT + (size_t)v*TT + t] = sbuf[cl*129 + m];
                    }
                }
            }
        }
    }
}

// ------------------------- tokens from keys -------------------------
__global__ void k_tok(float* __restrict__ out, int write_tok){
    int i = blockIdx.x*256 + threadIdx.x;
    if (i < MM && write_tok){
        ull key = g_tokkey[i];
        unsigned v = 0xFFFFFFFFu - (unsigned)(key & 0xFFFFFFFFu);
        out[(size_t)BB*VV*TT + i] = (float)v;   // i = b*TT + t
    }
}

// ------------------------- launch -------------------------
extern "C" void kernel_launch(void* const* d_in, const int* in_sizes, int n_in,
                              void* d_out, int out_size){
    const float* enc_feat = (const float*)d_in[0];
    const float* W_fp   = (const float*)d_in[1];
    const float* b_fp   = (const float*)d_in[2];
    const float* W_enc  = (const float*)d_in[3];
    const float* b_enc  = (const float*)d_in[4];
    const float* W_dec  = (const float*)d_in[5];
    const float* b_dec  = (const float*)d_in[6];
    const float* W_full = (const float*)d_in[7];
    const float* b_full = (const float*)d_in[8];
    const float* W_comb = (const float*)d_in[9];
    const float* b_comb = (const float*)d_in[10];
    const float* embed  = (const float*)d_in[11];
    const float* W_ih   = (const float*)d_in[12];
    const float* b_ih   = (const float*)d_in[13];
    const float* W_hh   = (const float*)d_in[14];
    const float* b_hh   = (const float*)d_in[15];
    const float* W_proj = (const float*)d_in[16];
    const float* b_proj = (const float*)d_in[17];
    const int* start    = (n_in >= 19) ? (const int*)d_in[18] : nullptr;
    float* out = (float*)d_out;

    k_rst<<<(MM + 255)/256, 256>>>();
    k_p0<<<BB, 256>>>(embed, start);
    k_p1<<<dim3(49, 8), 256>>>(enc_feat, W_fp, b_fp);
    k_h0<<<dim3(BB, 4), 128>>>();
    k_p2<<<dim3(49, 4), 256>>>(W_enc, b_enc);

    k_step<<<NBLK, 256>>>(W_dec, b_dec, W_full, b_full, W_comb, b_comb,
                          W_ih, b_ih, W_hh, b_hh);

    k_sf<<<dim3(76, 79), 256>>>(W_proj, b_proj, out);

    int write_tok = (out_size >= BB*VV*TT + MM) ? 1 : 0;
    k_tok<<<(MM + 255)/256, 256>>>(out, write_tok);
}

// round 14
// speedup vs baseline: 1.4064x; 1.4064x over previous
#include <cuda_runtime.h>
#include <cuda_bf16.h>
#include <math.h>
#include <cstdint>

#define BB 64
#define HH 512
#define AA 256
#define VV 10000
#define TT 151
#define LL 49
#define G3 1536
#define MM (BB*TT)
#define NBLK 128

typedef unsigned long long ull;

#define FMA2(acc, av, wv) asm("fma.rn.f32x2 %0, %1, %2, %0;" : "+l"(acc) : "l"(av), "l"(wv))

// ------------------------- device scratch (static, no allocs) -------------------------
__device__ float g_enc [BB*LL*HH];       // [b][l][d]  == row-major [3136][512]
__device__ float g_att1[BB*LL*AA];       // [b][l][a]
__device__ float g_h   [BB*HH];
__device__ float g_inp [BB*HH];
__device__ float g_ctx [BB*HH];
__device__ float g_comb[BB*HH];
__device__ float g_att2p[8][BB*AA];      // att2 k-split partials
__device__ float g_combp[16][BB*HH];     // comb k-split partials
__device__ float g_ghp [4][BB*G3];       // gh partials
__device__ float g_gip [4][BB*G3];       // gi partials
__device__ float g_ghsum[BB*G3];         // reduced gh + b_hh
__device__ float g_seq [BB*TT*HH];       // [b][t][d] == row-major [9664][512]
__device__ ull   g_tokkey[MM];
__device__ unsigned g_flag[NBLK*32];     // one 128B slot per CTA

__device__ __forceinline__ unsigned ordf(float f){
    unsigned u = __float_as_uint(f);
    return (u & 0x80000000u) ? ~u : (u | 0x80000000u);
}

// ------------------------- grid barrier: per-CTA flag slots, tight spin (proven round-9) ----
__device__ __forceinline__ void gsync(int epoch){
    __syncthreads();
    if (threadIdx.x == 0){
        asm volatile("st.release.gpu.global.u32 [%0], %1;"
                     :: "l"(&g_flag[blockIdx.x*32]), "r"((unsigned)epoch) : "memory");
    }
    if (threadIdx.x < NBLK){
        unsigned v;
        do {
            asm volatile("ld.acquire.gpu.global.u32 %0, [%1];"
                         : "=r"(v) : "l"(&g_flag[threadIdx.x*32]) : "memory");
        } while (v < (unsigned)epoch);
    }
    __syncthreads();
}

// ------------------------- reset flags + token keys -------------------------
__global__ void k_rst(){
    int i = blockIdx.x*256 + threadIdx.x;
    if (i < NBLK*32) g_flag[i] = 0u;
    if (i < MM) g_tokkey[i] = 0ULL;
}

// ------------------------- P0: inp0 = embed[start], seq[:,0,:] -------------------------
__global__ void k_p0(const float* __restrict__ embed, const int* __restrict__ start){
    int b = blockIdx.x;
    int st = start ? start[0] : 1;
    for (int d = threadIdx.x; d < HH; d += blockDim.x){
        float v = embed[(size_t)st*HH + d];
        g_inp[b*HH + d] = v;
        g_seq[((size_t)b*TT + 0)*HH + d] = v;
    }
}

// ------------------------- 64x64 microtile, FFMA2 packed (Ws stride 66) -------------------------
__device__ __forceinline__ void mt32_2(const float* __restrict__ As, const float* __restrict__ Ws,
                                       int tx, int ty, ull acc2[4][2]){
    #pragma unroll 8
    for (int kk = 0; kk < 32; kk++){
        ull a2[4], w2[2];
        #pragma unroll
        for (int i = 0; i < 4; i++){
            float av = As[(ty*4+i)*33 + kk];
            asm("mov.b64 %0, {%1, %2};" : "=l"(a2[i]) : "f"(av), "f"(av));
        }
        w2[0] = *(const ull*)&Ws[kk*66 + tx*4];
        w2[1] = *(const ull*)&Ws[kk*66 + tx*4 + 2];
        #pragma unroll
        for (int i = 0; i < 4; i++){
            FMA2(acc2[i][0], a2[i], w2[0]);
            FMA2(acc2[i][1], a2[i], w2[1]);
        }
    }
}

__device__ __forceinline__ void unpack44(ull acc2[4][2], float acc[4][4]){
    #pragma unroll
    for (int i = 0; i < 4; i++){
        asm("mov.b64 {%0, %1}, %2;" : "=f"(acc[i][0]), "=f"(acc[i][1]) : "l"(acc2[i][0]));
        asm("mov.b64 {%0, %1}, %2;" : "=f"(acc[i][2]), "=f"(acc[i][3]) : "l"(acc2[i][1]));
    }
}

// ------------------------- P1: enc = X^T @ W_fp + b_fp (tiled GEMM, M=3136) -------------------------
__global__ void __launch_bounds__(256)
k_p1(const float* __restrict__ X, const float* __restrict__ Wfp, const float* __restrict__ bfp){
    __shared__ __align__(16) float As[64*33];
    __shared__ __align__(16) float Ws[32*66];
    int m0 = blockIdx.x*64, n0 = blockIdx.y*64;
    int tid = threadIdx.x, tx = tid & 15, ty = tid >> 4;
    ull acc2[4][2] = {{0ULL,0ULL},{0ULL,0ULL},{0ULL,0ULL},{0ULL,0ULL}};
    for (int kc = 0; kc < HH; kc += 32){
        __syncthreads();
        #pragma unroll
        for (int i = 0; i < 8; i++){
            int idx = tid + i*256; int mm = idx >> 5, kk = idx & 31;
            int m = m0 + mm; int b = m / LL; int l = m - b*LL;
            As[mm*33 + kk] = X[((size_t)b*HH + kc + kk)*LL + l];
        }
        #pragma unroll
        for (int i = 0; i < 8; i++){
            int idx = tid + i*256; int kk = idx >> 6, n = idx & 63;
            Ws[kk*66 + n] = Wfp[(size_t)(kc+kk)*HH + n0 + n];
        }
        __syncthreads();
        mt32_2(As, Ws, tx, ty, acc2);
    }
    float acc[4][4]; unpack44(acc2, acc);
    #pragma unroll
    for (int j = 0; j < 4; j++){
        float bv = bfp[n0 + tx*4 + j];
        #pragma unroll
        for (int i = 0; i < 4; i++)
            g_enc[(size_t)(m0 + ty*4 + i)*HH + n0 + tx*4 + j] = acc[i][j] + bv;
    }
}

// ------------------------- h0 = mean over l of enc -------------------------
__global__ void k_h0(){
    int b = blockIdx.x;
    int d = blockIdx.y*128 + threadIdx.x;
    float s = 0.f;
    #pragma unroll 7
    for (int l = 0; l < LL; l++)
        s += g_enc[((size_t)b*LL + l)*HH + d];
    g_h[b*HH + d] = s * (1.f/(float)LL);
}

// ------------------------- P2: att1 = enc @ W_enc + b_enc (tiled GEMM) -------------------------
__global__ void __launch_bounds__(256)
k_p2(const float* __restrict__ Wenc, const float* __restrict__ benc){
    __shared__ __align__(16) float As[64*33];
    __shared__ __align__(16) float Ws[32*66];
    int m0 = blockIdx.x*64, n0 = blockIdx.y*64;
    int tid = threadIdx.x, tx = tid & 15, ty = tid >> 4;
    ull acc2[4][2] = {{0ULL,0ULL},{0ULL,0ULL},{0ULL,0ULL},{0ULL,0ULL}};
    for (int kc = 0; kc < HH; kc += 32){
        __syncthreads();
        #pragma unroll
        for (int i = 0; i < 8; i++){
            int idx = tid + i*256; int mm = idx >> 5, kk = idx & 31;
            As[mm*33 + kk] = g_enc[(size_t)(m0 + mm)*HH + kc + kk];
        }
        #pragma unroll
        for (int i = 0; i < 8; i++){
            int idx = tid + i*256; int kk = idx >> 6, n = idx & 63;
            Ws[kk*66 + n] = Wenc[(size_t)(kc+kk)*AA + n0 + n];
        }
        __syncthreads();
        mt32_2(As, Ws, tx, ty, acc2);
    }
    float acc[4][4]; unpack44(acc2, acc);
    #pragma unroll
    for (int j = 0; j < 4; j++){
        float bv = benc[n0 + tx*4 + j];
        #pragma unroll
        for (int i = 0; i < 4; i++)
            g_att1[(size_t)(m0 + ty*4 + i)*AA + n0 + tx*4 + j] = acc[i][j] + bv;
    }
}

// ------------------------- persistent step kernel: 150 steps, 6 phases, prefetch + FFMA2 ------------
__global__ void __launch_bounds__(256)
k_step(const float* __restrict__ Wdec,  const float* __restrict__ bdec,
       const float* __restrict__ Wfull, const float* __restrict__ bfull,
       const float* __restrict__ Wcomb, const float* __restrict__ bcomb,
       const float* __restrict__ Wih,   const float* __restrict__ bih,
       const float* __restrict__ Whh,   const float* __restrict__ bhh)
{
    __shared__ __align__(16) float As[64*33];
    __shared__ __align__(16) float Ws[32*66];
    const int blk = blockIdx.x, tid = threadIdx.x;
    const int tx = tid & 15, ty = tid >> 4;
    const int warp = tid >> 5, lane = tid & 31;
    int ep = 0;

    for (int t = 1; t < TT; t++){
        // ======== P1: att2 partials (blk<32) + gh partials (blk>=32) ========
        if (blk < 32){
            int at = blk & 3, ks = blk >> 2;
            int n0 = at*64, k0 = ks*64;
            ull acc2[4][2] = {{0ULL,0ULL},{0ULL,0ULL},{0ULL,0ULL},{0ULL,0ULL}};
            float pa[8], pw[8];
            #pragma unroll
            for (int i = 0; i < 8; i++){
                int idx = tid + i*256; int b = idx >> 5, kk = idx & 31;
                pa[i] = __ldcg(&g_h[b*HH + k0 + kk]);
            }
            #pragma unroll
            for (int i = 0; i < 8; i++){
                int idx = tid + i*256; int n = idx & 63, kk = idx >> 6;
                pw[i] = Wdec[(size_t)(k0+kk)*AA + n0 + n];
            }
            #pragma unroll
            for (int s = 0; s < 2; s++){
                __syncthreads();
                #pragma unroll
                for (int i = 0; i < 8; i++){
                    int idx = tid + i*256; int b = idx >> 5, kk = idx & 31;
                    As[b*33 + kk] = pa[i];
                }
                #pragma unroll
                for (int i = 0; i < 8; i++){
                    int idx = tid + i*256; int n = idx & 63, kk = idx >> 6;
                    Ws[kk*66 + n] = pw[i];
                }
                __syncthreads();
                if (s == 0){
                    int kb = k0 + 32;
                    #pragma unroll
                    for (int i = 0; i < 8; i++){
                        int idx = tid + i*256; int b = idx >> 5, kk = idx & 31;
                        pa[i] = __ldcg(&g_h[b*HH + kb + kk]);
                    }
                    #pragma unroll
                    for (int i = 0; i < 8; i++){
                        int idx = tid + i*256; int n = idx & 63, kk = idx >> 6;
                        pw[i] = Wdec[(size_t)(kb+kk)*AA + n0 + n];
                    }
                }
                mt32_2(As, Ws, tx, ty, acc2);
            }
            float acc[4][4]; unpack44(acc2, acc);
            float* outp = g_att2p[ks];
            #pragma unroll
            for (int i = 0; i < 4; i++)
                #pragma unroll
                for (int j = 0; j < 4; j++)
                    outp[(ty*4+i)*AA + n0 + tx*4 + j] = acc[i][j];
        } else {
            int rem = blk - 32;
            int jt = rem % 24, ks = rem / 24;
            int j0 = jt*64, k0 = ks*128;
            ull acc2[4][2] = {{0ULL,0ULL},{0ULL,0ULL},{0ULL,0ULL},{0ULL,0ULL}};
            float pa[8], pw[8];
            #pragma unroll
            for (int i = 0; i < 8; i++){
                int idx = tid + i*256; int b = idx >> 5, kk = idx & 31;
                pa[i] = __ldcg(&g_h[b*HH + k0 + kk]);
            }
            #pragma unroll
            for (int i = 0; i < 8; i++){
                int idx = tid + i*256; int kk = idx & 31, j = idx >> 5;
                pw[i] = Whh[(size_t)(j0+j)*HH + k0 + kk];
            }
            #pragma unroll
            for (int s = 0; s < 4; s++){
                __syncthreads();
                #pragma unroll
                for (int i = 0; i < 8; i++){
                    int idx = tid + i*256; int b = idx >> 5, kk = idx & 31;
                    As[b*33 + kk] = pa[i];
                }
                #pragma unroll
                for (int i = 0; i < 8; i++){
                    int idx = tid + i*256; int kk = idx & 31, j = idx >> 5;
                    Ws[kk*66 + j] = pw[i];
                }
                __syncthreads();
                if (s < 3){
                    int kb = k0 + (s+1)*32;
                    #pragma unroll
                    for (int i = 0; i < 8; i++){
                        int idx = tid + i*256; int b = idx >> 5, kk = idx & 31;
                        pa[i] = __ldcg(&g_h[b*HH + kb + kk]);
                    }
                    #pragma unroll
                    for (int i = 0; i < 8; i++){
                        int idx = tid + i*256; int kk = idx & 31, j = idx >> 5;
                        pw[i] = Whh[(size_t)(j0+j)*HH + kb + kk];
                    }
                }
                mt32_2(As, Ws, tx, ty, acc2);
            }
            float acc[4][4]; unpack44(acc2, acc);
            float* outp = g_ghp[ks];
            #pragma unroll
            for (int i = 0; i < 4; i++)
                #pragma unroll
                for (int j = 0; j < 4; j++)
                    outp[(ty*4+i)*G3 + j0 + tx*4 + j] = acc[i][j];
        }
        ep++; gsync(ep);

        // ======== P2: per-batch attention (blk<64) | gh reduce (blk>=64) ========
        if (blk < 64){
            int b = blk;
            {
                int a = tid;
                float s = bdec[a];
                #pragma unroll
                for (int p = 0; p < 8; p++) s += __ldcg(&g_att2p[p][b*AA + a]);
                As[a] = s;
            }
            __syncthreads();
            for (int l = warp; l < LL; l += 8){
                const float* a1p = g_att1 + ((size_t)b*LL + l)*AA;
                float s = 0.f;
                #pragma unroll
                for (int k = 0; k < 8; k++){
                    int a = lane + k*32;
                    s = fmaf(tanhf(a1p[a] + As[a]), Wfull[a], s);
                }
                #pragma unroll
                for (int o = 16; o > 0; o >>= 1) s += __shfl_xor_sync(0xffffffffu, s, o);
                if (lane == 0) As[256 + l] = s + bfull[0];
            }
            __syncthreads();
            if (warp == 0){
                int l1 = lane, l2 = lane + 32;
                float e1 = (l1 < LL) ? As[256+l1] : -1e30f;
                float e2 = (l2 < LL) ? As[256+l2] : -1e30f;
                float m = fmaxf(e1, e2);
                #pragma unroll
                for (int o = 16; o > 0; o >>= 1) m = fmaxf(m, __shfl_xor_sync(0xffffffffu, m, o));
                float p1 = (l1 < LL) ? expf(e1 - m) : 0.f;
                float p2 = (l2 < LL) ? expf(e2 - m) : 0.f;
                float sm = p1 + p2;
                #pragma unroll
                for (int o = 16; o > 0; o >>= 1) sm += __shfl_xor_sync(0xffffffffu, sm, o);
                float inv = 1.f/sm;
                if (l1 < LL) As[320 + l1] = p1*inv;
                if (l2 < LL) As[320 + l2] = p2*inv;
            }
            __syncthreads();
            {
                int d0 = tid, d1 = tid + 256;
                const float* eb = g_enc + (size_t)b*LL*HH;
                float c0 = 0.f, c1 = 0.f;
                #pragma unroll 7
                for (int l = 0; l < LL; l++){
                    float al = As[320 + l];
                    c0 = fmaf(al, eb[l*HH + d0], c0);
                    c1 = fmaf(al, eb[l*HH + d1], c1);
                }
                g_ctx[b*HH + d0] = c0;
                g_ctx[b*HH + d1] = c1;
            }
        } else {
            int b = blk - 64;
            for (int j = tid; j < G3; j += 256){
                float s = bhh[j];
                #pragma unroll
                for (int p = 0; p < 4; p++) s += __ldcg(&g_ghp[p][b*G3 + j]);
                g_ghsum[b*G3 + j] = s;
            }
        }
        ep++; gsync(ep);

        // ======== P3: comb partials: [inp|ctx] @ W_comb ========
        {
            int nt = blk & 7, ks = blk >> 3;
            int n0 = nt*64, k0 = ks*64;
            ull acc2[4][2] = {{0ULL,0ULL},{0ULL,0ULL},{0ULL,0ULL},{0ULL,0ULL}};
            float pa[8], pw[8];
            #pragma unroll
            for (int i = 0; i < 8; i++){
                int idx = tid + i*256; int b = idx >> 5, kk = idx & 31;
                int k = k0 + kk;
                pa[i] = (k < HH) ? __ldcg(&g_inp[b*HH + k]) : __ldcg(&g_ctx[b*HH + (k - HH)]);
            }
            #pragma unroll
            for (int i = 0; i < 8; i++){
                int idx = tid + i*256; int n = idx & 63, kk = idx >> 6;
                pw[i] = Wcomb[(size_t)(k0+kk)*HH + n0 + n];
            }
            #pragma unroll
            for (int s = 0; s < 2; s++){
                __syncthreads();
                #pragma unroll
                for (int i = 0; i < 8; i++){
                    int idx = tid + i*256; int b = idx >> 5, kk = idx & 31;
                    As[b*33 + kk] = pa[i];
                }
                #pragma unroll
                for (int i = 0; i < 8; i++){
                    int idx = tid + i*256; int n = idx & 63, kk = idx >> 6;
                    Ws[kk*66 + n] = pw[i];
                }
                __syncthreads();
                if (s == 0){
                    int kb = k0 + 32;
                    #pragma unroll
                    for (int i = 0; i < 8; i++){
                        int idx = tid + i*256; int b = idx >> 5, kk = idx & 31;
                        int k = kb + kk;
                        pa[i] = (k < HH) ? __ldcg(&g_inp[b*HH + k]) : __ldcg(&g_ctx[b*HH + (k - HH)]);
                    }
                    #pragma unroll
                    for (int i = 0; i < 8; i++){
                        int idx = tid + i*256; int n = idx & 63, kk = idx >> 6;
                        pw[i] = Wcomb[(size_t)(kb+kk)*HH + n0 + n];
                    }
                }
                mt32_2(As, Ws, tx, ty, acc2);
            }
            float acc[4][4]; unpack44(acc2, acc);
            float* outp = g_combp[ks];
            #pragma unroll
            for (int i = 0; i < 4; i++)
                #pragma unroll
                for (int j = 0; j < 4; j++)
                    outp[(ty*4+i)*HH + n0 + tx*4 + j] = acc[i][j];
        }
        ep++; gsync(ep);

        // ======== P4: comb reduce + tanh ========
        {
            int i = blk*256 + tid;
            int n = i & 511;
            float s = bcomb[n];
            #pragma unroll
            for (int p = 0; p < 16; p++) s += __ldcg(&g_combp[p][i]);
            g_comb[i] = tanhf(s);
        }
        ep++; gsync(ep);

        // ======== P5: gi partials: comb @ W_ih^T (blk<96) ========
        if (blk < 96){
            int jt = blk % 24, ks = blk / 24;
            int j0 = jt*64, k0 = ks*128;
            ull acc2[4][2] = {{0ULL,0ULL},{0ULL,0ULL},{0ULL,0ULL},{0ULL,0ULL}};
            float pa[8], pw[8];
            #pragma unroll
            for (int i = 0; i < 8; i++){
                int idx = tid + i*256; int b = idx >> 5, kk = idx & 31;
                pa[i] = __ldcg(&g_comb[b*HH + k0 + kk]);
            }
            #pragma unroll
            for (int i = 0; i < 8; i++){
                int idx = tid + i*256; int kk = idx & 31, j = idx >> 5;
                pw[i] = Wih[(size_t)(j0+j)*HH + k0 + kk];
            }
            #pragma unroll
            for (int s = 0; s < 4; s++){
                __syncthreads();
                #pragma unroll
                for (int i = 0; i < 8; i++){
                    int idx = tid + i*256; int b = idx >> 5, kk = idx & 31;
                    As[b*33 + kk] = pa[i];
                }
                #pragma unroll
                for (int i = 0; i < 8; i++){
                    int idx = tid + i*256; int kk = idx & 31, j = idx >> 5;
                    Ws[kk*66 + j] = pw[i];
                }
                __syncthreads();
                if (s < 3){
                    int kb = k0 + (s+1)*32;
                    #pragma unroll
                    for (int i = 0; i < 8; i++){
                        int idx = tid + i*256; int b = idx >> 5, kk = idx & 31;
                        pa[i] = __ldcg(&g_comb[b*HH + kb + kk]);
                    }
                    #pragma unroll
                    for (int i = 0; i < 8; i++){
                        int idx = tid + i*256; int kk = idx & 31, j = idx >> 5;
                        pw[i] = Wih[(size_t)(j0+j)*HH + kb + kk];
                    }
                }
                mt32_2(As, Ws, tx, ty, acc2);
            }
            float acc[4][4]; unpack44(acc2, acc);
            float* outp = g_gip[ks];
            #pragma unroll
            for (int i = 0; i < 4; i++)
                #pragma unroll
                for (int j = 0; j < 4; j++)
                    outp[(ty*4+i)*G3 + j0 + tx*4 + j] = acc[i][j];
        }
        ep++; gsync(ep);

        // ======== P6: GRU pointwise -> h, inp, seq[t] ========
        {
            int i = blk*256 + tid;
            int b = i >> 9, j = i & 511;
            float gir = bih[j], giz = bih[512+j], gin = bih[1024+j];
            #pragma unroll
            for (int p = 0; p < 4; p++){
                const float* gi = g_gip[p] + (size_t)b*G3;
                gir += __ldcg(&gi[j]); giz += __ldcg(&gi[512+j]); gin += __ldcg(&gi[1024+j]);
            }
            const float* gh = g_ghsum + (size_t)b*G3;
            float ghr = __ldcg(&gh[j]), ghz = __ldcg(&gh[512+j]), ghn = __ldcg(&gh[1024+j]);
            float h = __ldcg(&g_h[i]);
            float r = 1.f/(1.f + expf(-(gir + ghr)));
            float z = 1.f/(1.f + expf(-(giz + ghz)));
            float n = tanhf(gin + r*ghn);
            float hn = (1.f - z)*n + z*h;
            g_h[i] = hn;
            g_inp[i] = hn;
            g_seq[((size_t)b*TT + t)*HH + j] = hn;
        }
        ep++; gsync(ep);
    }
}

// ------------------------- Final: res = seq @ W_proj + b_proj (FFMA2) + fused argmax -------------------------
__global__ void __launch_bounds__(256, 2)
k_sf(const float* __restrict__ Wp, const float* __restrict__ bp, float* __restrict__ out){
    __shared__ __align__(16) float sm[4224];    // As[16][132] | Bs[16][132]; reused as sbuf[32][129]
    float* As = sm;
    float* Bs = sm + 2112;
    int m0 = blockIdx.x*128, n0 = blockIdx.y*128;
    int tid = threadIdx.x, tx = tid & 15, ty = tid >> 4;
    ull acc2[8][4];
    #pragma unroll
    for (int i=0;i<8;i++)
        #pragma unroll
        for (int j=0;j<4;j++) acc2[i][j] = 0ULL;

    for (int kc = 0; kc < HH; kc += 16){
        __syncthreads();
        #pragma unroll
        for (int i = 0; i < 8; i++){
            int idx = tid + i*256;        // 128 m x 16 k
            int kk = idx & 15, m = idx >> 4;
            int r = m0 + m;
            As[kk*132 + m] = (r < MM) ? g_seq[(size_t)r*HH + kc + kk] : 0.f;
        }
        #pragma unroll
        for (int i = 0; i < 8; i++){
            int idx = tid + i*256;        // 16 k x 128 n
            int n = idx & 127, kk = idx >> 7;
            int v = n0 + n;
            Bs[kk*132 + n] = (v < VV) ? Wp[(size_t)(kc+kk)*VV + v] : 0.f;
        }
        __syncthreads();
        #pragma unroll 4
        for (int kk = 0; kk < 16; kk++){
            ull a2[8], w2[4];
            #pragma unroll
            for (int i = 0; i < 8; i++){
                float av = As[kk*132 + ty*8 + i];
                asm("mov.b64 %0, {%1, %2};" : "=l"(a2[i]) : "f"(av), "f"(av));
            }
            #pragma unroll
            for (int j = 0; j < 4; j++)
                w2[j] = *(const ull*)&Bs[kk*132 + tx*8 + 2*j];
            #pragma unroll
            for (int i = 0; i < 8; i++)
                #pragma unroll
                for (int j = 0; j < 4; j++)
                    FMA2(acc2[i][j], a2[i], w2[j]);
        }
    }
    float acc[8][8];
    #pragma unroll
    for (int i = 0; i < 8; i++)
        #pragma unroll
        for (int j = 0; j < 4; j++)
            asm("mov.b64 {%0, %1}, %2;" : "=f"(acc[i][2*j]), "=f"(acc[i][2*j+1]) : "l"(acc2[i][j]));
    #pragma unroll
    for (int j = 0; j < 8; j++){
        int v = n0 + tx*8 + j;
        float bj = (v < VV) ? bp[v] : 0.f;
        #pragma unroll
        for (int i = 0; i < 8; i++) acc[i][j] += bj;
    }

    // fused argmax: packed key = ordf(val)<<32 | (~v) -> max value, ties pick smaller v
    #pragma unroll
    for (int i = 0; i < 8; i++){
        int r = m0 + ty*8 + i;
        ull best = 0ULL;
        #pragma unroll
        for (int j = 0; j < 8; j++){
            int v = n0 + tx*8 + j;
            if (v < VV){
                ull key = ((ull)ordf(acc[i][j]) << 32) | (ull)(0xFFFFFFFFu - (unsigned)v);
                if (key > best) best = key;
            }
        }
        #pragma unroll
        for (int o = 8; o > 0; o >>= 1){
            ull other = __shfl_xor_sync(0xffffffffu, best, o);
            if (other > best) best = other;
        }
        if (tx == 0 && r < MM) atomicMax(&g_tokkey[r], best);
    }

    // transposed store via smem (32 output columns per pass)
    float* sbuf = sm;                     // [32][129]
    int lane = tid & 31, cbase = tid >> 5;
    for (int cg = 0; cg < 4; cg++){
        __syncthreads();
        if ((tx >> 2) == cg){
            #pragma unroll
            for (int j = 0; j < 8; j++){
                int cl = (tx & 3)*8 + j;
                #pragma unroll
                for (int i = 0; i < 8; i++)
                    sbuf[cl*129 + ty*8 + i] = acc[i][j];
            }
        }
        __syncthreads();
        #pragma unroll
        for (int cc = 0; cc < 4; cc++){
            int cl = cbase + cc*8;        // 0..31
            int v = n0 + cg*32 + cl;
            if (v < VV){
                #pragma unroll
                for (int q = 0; q < 4; q++){
                    int m = lane + q*32;
                    int r = m0 + m;
                    if (r < MM){
                        int b = r / TT;
                        int t = r - b*TT;
                        out[(size_t)b*VV*TT + (size_t)v*TT + t] = sbuf[cl*129 + m];
                    }
                }
            }
        }
    }
}

// ------------------------- tokens from keys -------------------------
__global__ void k_tok(float* __restrict__ out, int write_tok){
    int i = blockIdx.x*256 + threadIdx.x;
    if (i < MM && write_tok){
        ull key = g_tokkey[i];
        unsigned v = 0xFFFFFFFFu - (unsigned)(key & 0xFFFFFFFFu);
        out[(size_t)BB*VV*TT + i] = (float)v;   // i = b*TT + t
    }
}

// ------------------------- launch -------------------------
extern "C" void kernel_launch(void* const* d_in, const int* in_sizes, int n_in,
                              void* d_out, int out_size){
    const float* enc_feat = (const float*)d_in[0];
    const float* W_fp   = (const float*)d_in[1];
    const float* b_fp   = (const float*)d_in[2];
    const float* W_enc  = (const float*)d_in[3];
    const float* b_enc  = (const float*)d_in[4];
    const float* W_dec  = (const float*)d_in[5];
    const float* b_dec  = (const float*)d_in[6];
    const float* W_full = (const float*)d_in[7];
    const float* b_full = (const float*)d_in[8];
    const float* W_comb = (const float*)d_in[9];
    const float* b_comb = (const float*)d_in[10];
    const float* embed  = (const float*)d_in[11];
    const float* W_ih   = (const float*)d_in[12];
    const float* b_ih   = (const float*)d_in[13];
    const float* W_hh   = (const float*)d_in[14];
    const float* b_hh   = (const float*)d_in[15];
    const float* W_proj = (const float*)d_in[16];
    const float* b_proj = (const float*)d_in[17];
    const int* start    = (n_in >= 19) ? (const int*)d_in[18] : nullptr;
    float* out = (float*)d_out;

    k_rst<<<(MM + 255)/256, 256>>>();
    k_p0<<<BB, 256>>>(embed, start);
    k_p1<<<dim3(49, 8), 256>>>(enc_feat, W_fp, b_fp);
    k_h0<<<dim3(BB, 4), 128>>>();
    k_p2<<<dim3(49, 4), 256>>>(W_enc, b_enc);

    k_step<<<NBLK, 256>>>(W_dec, b_dec, W_full, b_full, W_comb, b_comb,
                          W_ih, b_ih, W_hh, b_hh);

    k_sf<<<dim3(76, 79), 256>>>(W_proj, b_proj, out);

    int write_tok = (out_size >= BB*VV*TT + MM) ? 1 : 0;
    k_tok<<<(MM + 255)/256, 256>>>(out, write_tok);
}

// round 15
// speedup vs baseline: 1.4098x; 1.0024x over previous
#include <cuda_runtime.h>
#include <cuda_bf16.h>
#include <math.h>
#include <cstdint>

#define BB 64
#define HH 512
#define AA 256
#define VV 10000
#define TT 151
#define LL 49
#define G3 1536
#define MM (BB*TT)
#define NBLK 128

typedef unsigned long long ull;

#define FMA2(acc, av, wv) asm("fma.rn.f32x2 %0, %1, %2, %0;" : "+l"(acc) : "l"(av), "l"(wv))

// ------------------------- device scratch (static, no allocs) -------------------------
__device__ float g_enc [BB*LL*HH];       // [b][l][d]  == row-major [3136][512]
__device__ float g_att1[BB*LL*AA];       // [b][l][a]
__device__ float g_h   [BB*HH];
__device__ float g_inp [BB*HH];
__device__ float g_ctx [BB*HH];
__device__ float g_comb[BB*HH];
__device__ float g_att2p[8][BB*AA];      // att2 k-split partials
__device__ float g_combp[16][BB*HH];     // comb k-split partials
__device__ float g_ghp [4][BB*G3];       // gh partials
__device__ float g_gip [4][BB*G3];       // gi partials
__device__ float g_ghsum[BB*G3];         // reduced gh + b_hh
__device__ float g_seq [BB*TT*HH];       // [b][t][d] == row-major [9664][512]
__device__ ull   g_tokkey[MM];
__device__ unsigned g_flag[NBLK*32];     // one 128B slot per CTA

__device__ __forceinline__ unsigned ordf(float f){
    unsigned u = __float_as_uint(f);
    return (u & 0x80000000u) ? ~u : (u | 0x80000000u);
}

// ------------------------- grid barrier: per-CTA flag slots, tight spin (proven) ----
__device__ __forceinline__ void gsync(int epoch){
    __syncthreads();
    if (threadIdx.x == 0){
        asm volatile("st.release.gpu.global.u32 [%0], %1;"
                     :: "l"(&g_flag[blockIdx.x*32]), "r"((unsigned)epoch) : "memory");
    }
    if (threadIdx.x < NBLK){
        unsigned v;
        do {
            asm volatile("ld.acquire.gpu.global.u32 %0, [%1];"
                         : "=r"(v) : "l"(&g_flag[threadIdx.x*32]) : "memory");
        } while (v < (unsigned)epoch);
    }
    __syncthreads();
}

// ------------------------- launch 0: flags + token keys + P0 (inp0/seq[0]) -------------------------
__global__ void k_init(const float* __restrict__ embed, const int* __restrict__ start){
    int i = blockIdx.x*256 + threadIdx.x;      // grid 128*256 = 32768
    if (i < NBLK*32) g_flag[i] = 0u;
    if (i < MM) g_tokkey[i] = 0ULL;
    {
        int b = i >> 9, d = i & 511;           // covers all 64*512
        int st = start ? start[0] : 1;
        float v = embed[(size_t)st*HH + d];
        g_inp[b*HH + d] = v;
        g_seq[((size_t)b*TT + 0)*HH + d] = v;
    }
}

// ------------------------- 64x64 microtile, FFMA2 packed (Ws stride 66) -------------------------
__device__ __forceinline__ void mt32_2(const float* __restrict__ As, const float* __restrict__ Ws,
                                       int tx, int ty, ull acc2[4][2]){
    #pragma unroll 8
    for (int kk = 0; kk < 32; kk++){
        ull a2[4], w2[2];
        #pragma unroll
        for (int i = 0; i < 4; i++){
            float av = As[(ty*4+i)*33 + kk];
            asm("mov.b64 %0, {%1, %2};" : "=l"(a2[i]) : "f"(av), "f"(av));
        }
        w2[0] = *(const ull*)&Ws[kk*66 + tx*4];
        w2[1] = *(const ull*)&Ws[kk*66 + tx*4 + 2];
        #pragma unroll
        for (int i = 0; i < 4; i++){
            FMA2(acc2[i][0], a2[i], w2[0]);
            FMA2(acc2[i][1], a2[i], w2[1]);
        }
    }
}

__device__ __forceinline__ void unpack44(ull acc2[4][2], float acc[4][4]){
    #pragma unroll
    for (int i = 0; i < 4; i++){
        asm("mov.b64 {%0, %1}, %2;" : "=f"(acc[i][0]), "=f"(acc[i][1]) : "l"(acc2[i][0]));
        asm("mov.b64 {%0, %1}, %2;" : "=f"(acc[i][2]), "=f"(acc[i][3]) : "l"(acc2[i][1]));
    }
}

// ------------------------- launch 1: P1: enc = X^T @ W_fp + b_fp (tiled GEMM, M=3136) ---------------
__global__ void __launch_bounds__(256)
k_p1(const float* __restrict__ X, const float* __restrict__ Wfp, const float* __restrict__ bfp){
    __shared__ __align__(16) float As[64*33];
    __shared__ __align__(16) float Ws[32*66];
    int m0 = blockIdx.x*64, n0 = blockIdx.y*64;
    int tid = threadIdx.x, tx = tid & 15, ty = tid >> 4;
    ull acc2[4][2] = {{0ULL,0ULL},{0ULL,0ULL},{0ULL,0ULL},{0ULL,0ULL}};
    for (int kc = 0; kc < HH; kc += 32){
        __syncthreads();
        #pragma unroll
        for (int i = 0; i < 8; i++){
            int idx = tid + i*256; int mm = idx >> 5, kk = idx & 31;
            int m = m0 + mm; int b = m / LL; int l = m - b*LL;
            As[mm*33 + kk] = X[((size_t)b*HH + kc + kk)*LL + l];
        }
        #pragma unroll
        for (int i = 0; i < 8; i++){
            int idx = tid + i*256; int kk = idx >> 6, n = idx & 63;
            Ws[kk*66 + n] = Wfp[(size_t)(kc+kk)*HH + n0 + n];
        }
        __syncthreads();
        mt32_2(As, Ws, tx, ty, acc2);
    }
    float acc[4][4]; unpack44(acc2, acc);
    #pragma unroll
    for (int j = 0; j < 4; j++){
        float bv = bfp[n0 + tx*4 + j];
        #pragma unroll
        for (int i = 0; i < 4; i++)
            g_enc[(size_t)(m0 + ty*4 + i)*HH + n0 + tx*4 + j] = acc[i][j] + bv;
    }
}

// ------------------------- launch 2: P2 (att1 GEMM) + h0 mean fused -------------------------
__global__ void __launch_bounds__(256)
k_pre2(const float* __restrict__ Wenc, const float* __restrict__ benc){
    __shared__ __align__(16) float As[64*33];
    __shared__ __align__(16) float Ws[32*66];
    int m0 = blockIdx.x*64, n0 = blockIdx.y*64;
    int tid = threadIdx.x, tx = tid & 15, ty = tid >> 4;
    ull acc2[4][2] = {{0ULL,0ULL},{0ULL,0ULL},{0ULL,0ULL},{0ULL,0ULL}};
    for (int kc = 0; kc < HH; kc += 32){
        __syncthreads();
        #pragma unroll
        for (int i = 0; i < 8; i++){
            int idx = tid + i*256; int mm = idx >> 5, kk = idx & 31;
            As[mm*33 + kk] = g_enc[(size_t)(m0 + mm)*HH + kc + kk];
        }
        #pragma unroll
        for (int i = 0; i < 8; i++){
            int idx = tid + i*256; int kk = idx >> 6, n = idx & 63;
            Ws[kk*66 + n] = Wenc[(size_t)(kc+kk)*AA + n0 + n];
        }
        __syncthreads();
        mt32_2(As, Ws, tx, ty, acc2);
    }
    float acc[4][4]; unpack44(acc2, acc);
    #pragma unroll
    for (int j = 0; j < 4; j++){
        float bv = benc[n0 + tx*4 + j];
        #pragma unroll
        for (int i = 0; i < 4; i++)
            g_att1[(size_t)(m0 + ty*4 + i)*AA + n0 + tx*4 + j] = acc[i][j] + bv;
    }
    // fused h0: first 128 CTA-units compute g_h = mean_l(g_enc)
    {
        int u = blockIdx.y*49 + blockIdx.x;        // 0..195
        if (u < 128){
            int b = u >> 1;
            int d = (u & 1)*256 + tid;
            float s = 0.f;
            #pragma unroll 7
            for (int l = 0; l < LL; l++)
                s += g_enc[((size_t)b*LL + l)*HH + d];
            g_h[b*HH + d] = s * (1.f/(float)LL);
        }
    }
}

// ------------------------- launch 3 (PROFILED): persistent step kernel, byte-identical core ---------
__global__ void __launch_bounds__(256)
k_step(const float* __restrict__ Wdec,  const float* __restrict__ bdec,
       const float* __restrict__ Wfull, const float* __restrict__ bfull,
       const float* __restrict__ Wcomb, const float* __restrict__ bcomb,
       const float* __restrict__ Wih,   const float* __restrict__ bih,
       const float* __restrict__ Whh,   const float* __restrict__ bhh)
{
    __shared__ __align__(16) float As[64*33];
    __shared__ __align__(16) float Ws[32*66];
    const int blk = blockIdx.x, tid = threadIdx.x;
    const int tx = tid & 15, ty = tid >> 4;
    const int warp = tid >> 5, lane = tid & 31;
    int ep = 0;

    for (int t = 1; t < TT; t++){
        // ======== P1: att2 partials (blk<32) + gh partials (blk>=32) ========
        if (blk < 32){
            int at = blk & 3, ks = blk >> 2;
            int n0 = at*64, k0 = ks*64;
            ull acc2[4][2] = {{0ULL,0ULL},{0ULL,0ULL},{0ULL,0ULL},{0ULL,0ULL}};
            float pa[8], pw[8];
            #pragma unroll
            for (int i = 0; i < 8; i++){
                int idx = tid + i*256; int b = idx >> 5, kk = idx & 31;
                pa[i] = __ldcg(&g_h[b*HH + k0 + kk]);
            }
            #pragma unroll
            for (int i = 0; i < 8; i++){
                int idx = tid + i*256; int n = idx & 63, kk = idx >> 6;
                pw[i] = Wdec[(size_t)(k0+kk)*AA + n0 + n];
            }
            #pragma unroll
            for (int s = 0; s < 2; s++){
                __syncthreads();
                #pragma unroll
                for (int i = 0; i < 8; i++){
                    int idx = tid + i*256; int b = idx >> 5, kk = idx & 31;
                    As[b*33 + kk] = pa[i];
                }
                #pragma unroll
                for (int i = 0; i < 8; i++){
                    int idx = tid + i*256; int n = idx & 63, kk = idx >> 6;
                    Ws[kk*66 + n] = pw[i];
                }
                __syncthreads();
                if (s == 0){
                    int kb = k0 + 32;
                    #pragma unroll
                    for (int i = 0; i < 8; i++){
                        int idx = tid + i*256; int b = idx >> 5, kk = idx & 31;
                        pa[i] = __ldcg(&g_h[b*HH + kb + kk]);
                    }
                    #pragma unroll
                    for (int i = 0; i < 8; i++){
                        int idx = tid + i*256; int n = idx & 63, kk = idx >> 6;
                        pw[i] = Wdec[(size_t)(kb+kk)*AA + n0 + n];
                    }
                }
                mt32_2(As, Ws, tx, ty, acc2);
            }
            float acc[4][4]; unpack44(acc2, acc);
            float* outp = g_att2p[ks];
            #pragma unroll
            for (int i = 0; i < 4; i++)
                #pragma unroll
                for (int j = 0; j < 4; j++)
                    outp[(ty*4+i)*AA + n0 + tx*4 + j] = acc[i][j];
        } else {
            int rem = blk - 32;
            int jt = rem % 24, ks = rem / 24;
            int j0 = jt*64, k0 = ks*128;
            ull acc2[4][2] = {{0ULL,0ULL},{0ULL,0ULL},{0ULL,0ULL},{0ULL,0ULL}};
            float pa[8], pw[8];
            #pragma unroll
            for (int i = 0; i < 8; i++){
                int idx = tid + i*256; int b = idx >> 5, kk = idx & 31;
                pa[i] = __ldcg(&g_h[b*HH + k0 + kk]);
            }
            #pragma unroll
            for (int i = 0; i < 8; i++){
                int idx = tid + i*256; int kk = idx & 31, j = idx >> 5;
                pw[i] = Whh[(size_t)(j0+j)*HH + k0 + kk];
            }
            #pragma unroll
            for (int s = 0; s < 4; s++){
                __syncthreads();
                #pragma unroll
                for (int i = 0; i < 8; i++){
                    int idx = tid + i*256; int b = idx >> 5, kk = idx & 31;
                    As[b*33 + kk] = pa[i];
                }
                #pragma unroll
                for (int i = 0; i < 8; i++){
                    int idx = tid + i*256; int kk = idx & 31, j = idx >> 5;
                    Ws[kk*66 + j] = pw[i];
                }
                __syncthreads();
                if (s < 3){
                    int kb = k0 + (s+1)*32;
                    #pragma unroll
                    for (int i = 0; i < 8; i++){
                        int idx = tid + i*256; int b = idx >> 5, kk = idx & 31;
                        pa[i] = __ldcg(&g_h[b*HH + kb + kk]);
                    }
                    #pragma unroll
                    for (int i = 0; i < 8; i++){
                        int idx = tid + i*256; int kk = idx & 31, j = idx >> 5;
                        pw[i] = Whh[(size_t)(j0+j)*HH + kb + kk];
                    }
                }
                mt32_2(As, Ws, tx, ty, acc2);
            }
            float acc[4][4]; unpack44(acc2, acc);
            float* outp = g_ghp[ks];
            #pragma unroll
            for (int i = 0; i < 4; i++)
                #pragma unroll
                for (int j = 0; j < 4; j++)
                    outp[(ty*4+i)*G3 + j0 + tx*4 + j] = acc[i][j];
        }
        ep++; gsync(ep);

        // ======== P2: per-batch attention (blk<64) | gh reduce (blk>=64) ========
        if (blk < 64){
            int b = blk;
            {
                int a = tid;
                float s = bdec[a];
                #pragma unroll
                for (int p = 0; p < 8; p++) s += __ldcg(&g_att2p[p][b*AA + a]);
                As[a] = s;
            }
            __syncthreads();
            for (int l = warp; l < LL; l += 8){
                const float* a1p = g_att1 + ((size_t)b*LL + l)*AA;
                float s = 0.f;
                #pragma unroll
                for (int k = 0; k < 8; k++){
                    int a = lane + k*32;
                    s = fmaf(tanhf(a1p[a] + As[a]), Wfull[a], s);
                }
                #pragma unroll
                for (int o = 16; o > 0; o >>= 1) s += __shfl_xor_sync(0xffffffffu, s, o);
                if (lane == 0) As[256 + l] = s + bfull[0];
            }
            __syncthreads();
            if (warp == 0){
                int l1 = lane, l2 = lane + 32;
                float e1 = (l1 < LL) ? As[256+l1] : -1e30f;
                float e2 = (l2 < LL) ? As[256+l2] : -1e30f;
                float m = fmaxf(e1, e2);
                #pragma unroll
                for (int o = 16; o > 0; o >>= 1) m = fmaxf(m, __shfl_xor_sync(0xffffffffu, m, o));
                float p1 = (l1 < LL) ? expf(e1 - m) : 0.f;
                float p2 = (l2 < LL) ? expf(e2 - m) : 0.f;
                float sm = p1 + p2;
                #pragma unroll
                for (int o = 16; o > 0; o >>= 1) sm += __shfl_xor_sync(0xffffffffu, sm, o);
                float inv = 1.f/sm;
                if (l1 < LL) As[320 + l1] = p1*inv;
                if (l2 < LL) As[320 + l2] = p2*inv;
            }
            __syncthreads();
            {
                int d0 = tid, d1 = tid + 256;
                const float* eb = g_enc + (size_t)b*LL*HH;
                float c0 = 0.f, c1 = 0.f;
                #pragma unroll 7
                for (int l = 0; l < LL; l++){
                    float al = As[320 + l];
                    c0 = fmaf(al, eb[l*HH + d0], c0);
                    c1 = fmaf(al, eb[l*HH + d1], c1);
                }
                g_ctx[b*HH + d0] = c0;
                g_ctx[b*HH + d1] = c1;
            }
        } else {
            int b = blk - 64;
            for (int j = tid; j < G3; j += 256){
                float s = bhh[j];
                #pragma unroll
                for (int p = 0; p < 4; p++) s += __ldcg(&g_ghp[p][b*G3 + j]);
                g_ghsum[b*G3 + j] = s;
            }
        }
        ep++; gsync(ep);

        // ======== P3: comb partials: [inp|ctx] @ W_comb ========
        {
            int nt = blk & 7, ks = blk >> 3;
            int n0 = nt*64, k0 = ks*64;
            ull acc2[4][2] = {{0ULL,0ULL},{0ULL,0ULL},{0ULL,0ULL},{0ULL,0ULL}};
            float pa[8], pw[8];
            #pragma unroll
            for (int i = 0; i < 8; i++){
                int idx = tid + i*256; int b = idx >> 5, kk = idx & 31;
                int k = k0 + kk;
                pa[i] = (k < HH) ? __ldcg(&g_inp[b*HH + k]) : __ldcg(&g_ctx[b*HH + (k - HH)]);
            }
            #pragma unroll
            for (int i = 0; i < 8; i++){
                int idx = tid + i*256; int n = idx & 63, kk = idx >> 6;
                pw[i] = Wcomb[(size_t)(k0+kk)*HH + n0 + n];
            }
            #pragma unroll
            for (int s = 0; s < 2; s++){
                __syncthreads();
                #pragma unroll
                for (int i = 0; i < 8; i++){
                    int idx = tid + i*256; int b = idx >> 5, kk = idx & 31;
                    As[b*33 + kk] = pa[i];
                }
                #pragma unroll
                for (int i = 0; i < 8; i++){
                    int idx = tid + i*256; int n = idx & 63, kk = idx >> 6;
                    Ws[kk*66 + n] = pw[i];
                }
                __syncthreads();
                if (s == 0){
                    int kb = k0 + 32;
                    #pragma unroll
                    for (int i = 0; i < 8; i++){
                        int idx = tid + i*256; int b = idx >> 5, kk = idx & 31;
                        int k = kb + kk;
                        pa[i] = (k < HH) ? __ldcg(&g_inp[b*HH + k]) : __ldcg(&g_ctx[b*HH + (k - HH)]);
                    }
                    #pragma unroll
                    for (int i = 0; i < 8; i++){
                        int idx = tid + i*256; int n = idx & 63, kk = idx >> 6;
                        pw[i] = Wcomb[(size_t)(kb+kk)*HH + n0 + n];
                    }
                }
                mt32_2(As, Ws, tx, ty, acc2);
            }
            float acc[4][4]; unpack44(acc2, acc);
            float* outp = g_combp[ks];
            #pragma unroll
            for (int i = 0; i < 4; i++)
                #pragma unroll
                for (int j = 0; j < 4; j++)
                    outp[(ty*4+i)*HH + n0 + tx*4 + j] = acc[i][j];
        }
        ep++; gsync(ep);

        // ======== P4: comb reduce + tanh ========
        {
            int i = blk*256 + tid;
            int n = i & 511;
            float s = bcomb[n];
            #pragma unroll
            for (int p = 0; p < 16; p++) s += __ldcg(&g_combp[p][i]);
            g_comb[i] = tanhf(s);
        }
        ep++; gsync(ep);

        // ======== P5: gi partials: comb @ W_ih^T (blk<96) ========
        if (blk < 96){
            int jt = blk % 24, ks = blk / 24;
            int j0 = jt*64, k0 = ks*128;
            ull acc2[4][2] = {{0ULL,0ULL},{0ULL,0ULL},{0ULL,0ULL},{0ULL,0ULL}};
            float pa[8], pw[8];
            #pragma unroll
            for (int i = 0; i < 8; i++){
                int idx = tid + i*256; int b = idx >> 5, kk = idx & 31;
                pa[i] = __ldcg(&g_comb[b*HH + k0 + kk]);
            }
            #pragma unroll
            for (int i = 0; i < 8; i++){
                int idx = tid + i*256; int kk = idx & 31, j = idx >> 5;
                pw[i] = Wih[(size_t)(j0+j)*HH + k0 + kk];
            }
            #pragma unroll
            for (int s = 0; s < 4; s++){
                __syncthreads();
                #pragma unroll
                for (int i = 0; i < 8; i++){
                    int idx = tid + i*256; int b = idx >> 5, kk = idx & 31;
                    As[b*33 + kk] = pa[i];
                }
                #pragma unroll
                for (int i = 0; i < 8; i++){
                    int idx = tid + i*256; int kk = idx & 31, j = idx >> 5;
                    Ws[kk*66 + j] = pw[i];
                }
                __syncthreads();
                if (s < 3){
                    int kb = k0 + (s+1)*32;
                    #pragma unroll
                    for (int i = 0; i < 8; i++){
                        int idx = tid + i*256; int b = idx >> 5, kk = idx & 31;
                        pa[i] = __ldcg(&g_comb[b*HH + kb + kk]);
                    }
                    #pragma unroll
                    for (int i = 0; i < 8; i++){
                        int idx = tid + i*256; int kk = idx & 31, j = idx >> 5;
                        pw[i] = Wih[(size_t)(j0+j)*HH + kb + kk];
                    }
                }
                mt32_2(As, Ws, tx, ty, acc2);
            }
            float acc[4][4]; unpack44(acc2, acc);
            float* outp = g_gip[ks];
            #pragma unroll
            for (int i = 0; i < 4; i++)
                #pragma unroll
                for (int j = 0; j < 4; j++)
                    outp[(ty*4+i)*G3 + j0 + tx*4 + j] = acc[i][j];
        }
        ep++; gsync(ep);

        // ======== P6: GRU pointwise -> h, inp, seq[t] ========
        {
            int i = blk*256 + tid;
            int b = i >> 9, j = i & 511;
            float gir = bih[j], giz = bih[512+j], gin = bih[1024+j];
            #pragma unroll
            for (int p = 0; p < 4; p++){
                const float* gi = g_gip[p] + (size_t)b*G3;
                gir += __ldcg(&gi[j]); giz += __ldcg(&gi[512+j]); gin += __ldcg(&gi[1024+j]);
            }
            const float* gh = g_ghsum + (size_t)b*G3;
            float ghr = __ldcg(&gh[j]), ghz = __ldcg(&gh[512+j]), ghn = __ldcg(&gh[1024+j]);
            float h = __ldcg(&g_h[i]);
            float r = 1.f/(1.f + expf(-(gir + ghr)));
            float z = 1.f/(1.f + expf(-(giz + ghz)));
            float n = tanhf(gin + r*ghn);
            float hn = (1.f - z)*n + z*h;
            g_h[i] = hn;
            g_inp[i] = hn;
            g_seq[((size_t)b*TT + t)*HH + j] = hn;
        }
        ep++; gsync(ep);
    }
}

// ------------------------- launch 4: res = seq @ W_proj + b_proj (FFMA2) + fused argmax -------------
__global__ void __launch_bounds__(256, 2)
k_sf(const float* __restrict__ Wp, const float* __restrict__ bp, float* __restrict__ out){
    __shared__ __align__(16) float sm[4224];    // As[16][132] | Bs[16][132]; reused as sbuf[32][129]
    float* As = sm;
    float* Bs = sm + 2112;
    int m0 = blockIdx.x*128, n0 = blockIdx.y*128;
    int tid = threadIdx.x, tx = tid & 15, ty = tid >> 4;
    ull acc2[8][4];
    #pragma unroll
    for (int i=0;i<8;i++)
        #pragma unroll
        for (int j=0;j<4;j++) acc2[i][j] = 0ULL;

    for (int kc = 0; kc < HH; kc += 16){
        __syncthreads();
        #pragma unroll
        for (int i = 0; i < 8; i++){
            int idx = tid + i*256;        // 128 m x 16 k
            int kk = idx & 15, m = idx >> 4;
            int r = m0 + m;
            As[kk*132 + m] = (r < MM) ? g_seq[(size_t)r*HH + kc + kk] : 0.f;
        }
        #pragma unroll
        for (int i = 0; i < 8; i++){
            int idx = tid + i*256;        // 16 k x 128 n
            int n = idx & 127, kk = idx >> 7;
            int v = n0 + n;
            Bs[kk*132 + n] = (v < VV) ? Wp[(size_t)(kc+kk)*VV + v] : 0.f;
        }
        __syncthreads();
        #pragma unroll 4
        for (int kk = 0; kk < 16; kk++){
            ull a2[8], w2[4];
            #pragma unroll
            for (int i = 0; i < 8; i++){
                float av = As[kk*132 + ty*8 + i];
                asm("mov.b64 %0, {%1, %2};" : "=l"(a2[i]) : "f"(av), "f"(av));
            }
            #pragma unroll
            for (int j = 0; j < 4; j++)
                w2[j] = *(const ull*)&Bs[kk*132 + tx*8 + 2*j];
            #pragma unroll
            for (int i = 0; i < 8; i++)
                #pragma unroll
                for (int j = 0; j < 4; j++)
                    FMA2(acc2[i][j], a2[i], w2[j]);
        }
    }
    float acc[8][8];
    #pragma unroll
    for (int i = 0; i < 8; i++)
        #pragma unroll
        for (int j = 0; j < 4; j++)
            asm("mov.b64 {%0, %1}, %2;" : "=f"(acc[i][2*j]), "=f"(acc[i][2*j+1]) : "l"(acc2[i][j]));
    #pragma unroll
    for (int j = 0; j < 8; j++){
        int v = n0 + tx*8 + j;
        float bj = (v < VV) ? bp[v] : 0.f;
        #pragma unroll
        for (int i = 0; i < 8; i++) acc[i][j] += bj;
    }

    // fused argmax: packed key = ordf(val)<<32 | (~v) -> max value, ties pick smaller v
    #pragma unroll
    for (int i = 0; i < 8; i++){
        int r = m0 + ty*8 + i;
        ull best = 0ULL;
        #pragma unroll
        for (int j = 0; j < 8; j++){
            int v = n0 + tx*8 + j;
            if (v < VV){
                ull key = ((ull)ordf(acc[i][j]) << 32) | (ull)(0xFFFFFFFFu - (unsigned)v);
                if (key > best) best = key;
            }
        }
        #pragma unroll
        for (int o = 8; o > 0; o >>= 1){
            ull other = __shfl_xor_sync(0xffffffffu, best, o);
            if (other > best) best = other;
        }
        if (tx == 0 && r < MM) atomicMax(&g_tokkey[r], best);
    }

    // transposed store via smem (32 output columns per pass)
    float* sbuf = sm;                     // [32][129]
    int lane = tid & 31, cbase = tid >> 5;
    for (int cg = 0; cg < 4; cg++){
        __syncthreads();
        if ((tx >> 2) == cg){
            #pragma unroll
            for (int j = 0; j < 8; j++){
                int cl = (tx & 3)*8 + j;
                #pragma unroll
                for (int i = 0; i < 8; i++)
                    sbuf[cl*129 + ty*8 + i] = acc[i][j];
            }
        }
        __syncthreads();
        #pragma unroll
        for (int cc = 0; cc < 4; cc++){
            int cl = cbase + cc*8;        // 0..31
            int v = n0 + cg*32 + cl;
            if (v < VV){
                #pragma unroll
                for (int q = 0; q < 4; q++){
                    int m = lane + q*32;
                    int r = m0 + m;
                    if (r < MM){
                        int b = r / TT;
                        int t = r - b*TT;
                        out[(size_t)b*VV*TT + (size_t)v*TT + t] = sbuf[cl*129 + m];
                    }
                }
            }
        }
    }
}

// ------------------------- launch 5: tokens from keys -------------------------
__global__ void k_tok(float* __restrict__ out, int write_tok){
    int i = blockIdx.x*256 + threadIdx.x;
    if (i < MM && write_tok){
        ull key = g_tokkey[i];
        unsigned v = 0xFFFFFFFFu - (unsigned)(key & 0xFFFFFFFFu);
        out[(size_t)BB*VV*TT + i] = (float)v;   // i = b*TT + t
    }
}

// ------------------------- launch -------------------------
extern "C" void kernel_launch(void* const* d_in, const int* in_sizes, int n_in,
                              void* d_out, int out_size){
    const float* enc_feat = (const float*)d_in[0];
    const float* W_fp   = (const float*)d_in[1];
    const float* b_fp   = (const float*)d_in[2];
    const float* W_enc  = (const float*)d_in[3];
    const float* b_enc  = (const float*)d_in[4];
    const float* W_dec  = (const float*)d_in[5];
    const float* b_dec  = (const float*)d_in[6];
    const float* W_full = (const float*)d_in[7];
    const float* b_full = (const float*)d_in[8];
    const float* W_comb = (const float*)d_in[9];
    const float* b_comb = (const float*)d_in[10];
    const float* embed  = (const float*)d_in[11];
    const float* W_ih   = (const float*)d_in[12];
    const float* b_ih   = (const float*)d_in[13];
    const float* W_hh   = (const float*)d_in[14];
    const float* b_hh   = (const float*)d_in[15];
    const float* W_proj = (const float*)d_in[16];
    const float* b_proj = (const float*)d_in[17];
    const int* start    = (n_in >= 19) ? (const int*)d_in[18] : nullptr;
    float* out = (float*)d_out;

    k_init<<<128, 256>>>(embed, start);                       // launch 0
    k_p1<<<dim3(49, 8), 256>>>(enc_feat, W_fp, b_fp);         // launch 1
    k_pre2<<<dim3(49, 4), 256>>>(W_enc, b_enc);               // launch 2

    k_step<<<NBLK, 256>>>(W_dec, b_dec, W_full, b_full,       // launch 3  <-- ncu target
                          W_comb, b_comb, W_ih, b_ih, W_hh, b_hh);

    k_sf<<<dim3(76, 79), 256>>>(W_proj, b_proj, out);         // launch 4

    int write_tok = (out_size >= BB*VV*TT + MM) ? 1 : 0;
    k_tok<<<(MM + 255)/256, 256>>>(out, write_tok);           // launch 5
}